// round 13
// baseline (speedup 1.0000x reference)
#include <cuda_runtime.h>

// Spatial GCN on a 24x24 grid: adj = D^-1 A + I (4-neighbor grid) => 5-point
// stencil with analytic 1/deg(neighbor) in {1/2, 1/3, 1/4}. Then elementwise
// weight, BatchNorm2d (batch stats), LeakyReLU(0.2).
//
// R12 (resubmit after infra failure): two lean high-occupancy passes
// exploiting L2 residency of x (75.5 MB < 126 MB L2, persists across
// launches). Pass1: stencil+stats only (pure DRAM read). Finalize:
// scale/shift. Pass2: recompute stencil from L2-hot x, normalize+LeakyReLU,
// stream out. Total DRAM traffic = 151 MB (minimum).

#define B_   64
#define C_   512
#define NN   576
#define BN_EPS 1e-4f
#define SLOPE  0.2f

#define TPB  288     // 2 chunk-slots of 144
#define U_   4
#define IPB  (2*U_)  // 8 images per block

__device__ float g_psum[C_ * B_];
__device__ float g_psq [C_ * B_];
__device__ float g_scale[C_];
__device__ float g_shift[C_];

__device__ __forceinline__ float invd(int d) {
    // d in {2,3,4}
    return d == 4 ? 0.25f : (d == 3 ? (1.0f / 3.0f) : 0.5f);
}

template <bool STATS>
__global__ __launch_bounds__(TPB, 4) void k_main(const float* __restrict__ x,
                                                 const float* __restrict__ w,
                                                 float* __restrict__ out) {
    __shared__ float xs[IPB * NN];                 // 18 KB staged images
    __shared__ float ps1[IPB * 144], ps2[IPB * 144];
    __shared__ float qs1[128], qs2[128];

    const int tid  = threadIdx.x;
    const int slot = tid >= 144;
    const int r    = tid - 144 * slot;             // chunk 0..143
    const int i    = r / 6;                        // row
    const int q    = r - 6 * i;                    // chunk-in-row
    const int g0   = blockIdx.x * IPB + slot * U_;
    const int c0   = g0 & (C_ - 1);
    const size_t off0 = (size_t)g0 * NN + r * 4;

    // batched center loads (MLP=4), then stage to smem
    float4 ct[U_];
    #pragma unroll
    for (int u = 0; u < U_; u++)
        ct[u] = *(const float4*)(x + off0 + u * NN);
    #pragma unroll
    for (int u = 0; u < U_; u++)
        *(float4*)(xs + (slot * U_ + u) * NN + r * 4) = ct[u];
    __syncthreads();

    // stencil coefficients (chunk-position only)
    const int rti = (i > 0) + (i < 23);
    const int rtu = (i > 1) + 1;                   // rowterm(i-1), valid iff i>0
    const int rtd = 1 + (i < 22);                  // rowterm(i+1), valid iff i<23
    const float cHi = invd(rti + 2);
    const float cHe = invd(rti + 1);
    const float cUi = invd(rtu + 2), cUe = invd(rtu + 1);
    const float cDi = invd(rtd + 2), cDe = invd(rtd + 1);

    const bool q0 = (q == 0), q5 = (q == 5);
    const bool hasU = (i > 0), hasD = (i < 23);
    const float cL0 = q0 ? 0.0f : cHi;
    const float cL1 = q0 ? cHe  : cHi;
    const float cR2 = q5 ? cHe  : cHi;
    const float cR3 = q5 ? 0.0f : cHi;
    const float vU = hasU ? 1.0f : 0.0f;
    const float vD = hasD ? 1.0f : 0.0f;
    const float cU0 = vU * (q0 ? cUe : cUi), cUm = vU * cUi, cU3 = vU * (q5 ? cUe : cUi);
    const float cD0 = vD * (q0 ? cDe : cDi), cDm = vD * cDi, cD3 = vD * (q5 ? cDe : cDi);

    const int upOff = hasU ? -24 : 0;              // clamped (coeff 0 when clamped)
    const int dnOff = hasD ?  24 : 0;
    const int lfOff = q0 ? 0 : -1;
    const int rgOff = q5 ? 0 :  4;

    float a1[U_], a2[U_];

    #pragma unroll
    for (int u = 0; u < U_; u++) {
        const float* xc = xs + (slot * U_ + u) * NN + r * 4;
        const float4 wv = __ldg((const float4*)(w + (c0 + u) * NN + r * 4));
        const float4 up = *(const float4*)(xc + upOff);
        const float4 dn = *(const float4*)(xc + dnOff);
        const float  lf = xc[lfOff];
        const float  rg = xc[rgOff];
        const float4 c4 = ct[u];

        const float s0 = c4.x + cL0 * lf   + cHi * c4.y + cU0 * up.x + cD0 * dn.x;
        const float s1 = c4.y + cL1 * c4.x + cHi * c4.z + cUm * up.y + cDm * dn.y;
        const float s2 = c4.z + cHi * c4.y + cR2 * c4.w + cUm * up.z + cDm * dn.z;
        const float s3 = c4.w + cHi * c4.z + cR3 * rg   + cU3 * up.w + cD3 * dn.w;

        const float y0 = s0 * wv.x, y1 = s1 * wv.y, y2 = s2 * wv.z, y3 = s3 * wv.w;

        if (STATS) {
            a1[u] = (y0 + y1) + (y2 + y3);
            a2[u] = (y0 * y0 + y1 * y1) + (y2 * y2 + y3 * y3);
        } else {
            const float sc = __ldg(&g_scale[c0 + u]);
            const float sh = __ldg(&g_shift[c0 + u]);
            float n0 = fmaf(y0, sc, sh), n1 = fmaf(y1, sc, sh);
            float n2 = fmaf(y2, sc, sh), n3 = fmaf(y3, sc, sh);
            n0 = (n0 >= 0.f) ? n0 : SLOPE * n0;
            n1 = (n1 >= 0.f) ? n1 : SLOPE * n1;
            n2 = (n2 >= 0.f) ? n2 : SLOPE * n2;
            n3 = (n3 >= 0.f) ? n3 : SLOPE * n3;
            *(float4*)(out + off0 + u * NN) = make_float4(n0, n1, n2, n3);
        }
    }

    if (STATS) {
        #pragma unroll
        for (int u = 0; u < U_; u++) {
            ps1[(slot * U_ + u) * 144 + r] = a1[u];
            ps2[(slot * U_ + u) * 144 + r] = a2[u];
        }
        __syncthreads();
        // stage 1: 128 threads sum 9 consecutive partials (144 = 16*9, so
        // groups never straddle an image)
        if (tid < 128) {
            float a = 0.f, b = 0.f;
            #pragma unroll
            for (int k = 0; k < 9; k++) { a += ps1[tid * 9 + k]; b += ps2[tid * 9 + k]; }
            qs1[tid] = a; qs2[tid] = b;
        }
        __syncthreads();
        // stage 2: one thread per image sums its 16 group partials
        if (tid < IPB) {
            float a = 0.f, b = 0.f;
            #pragma unroll
            for (int k = 0; k < 16; k++) { a += qs1[tid * 16 + k]; b += qs2[tid * 16 + k]; }
            const int bc = blockIdx.x * IPB + tid;
            const int bb = bc >> 9, cc = bc & (C_ - 1);
            g_psum[cc * B_ + bb] = a;
            g_psq [cc * B_ + bb] = b;
        }
    }
}

// ---------------- finalize ----------------
__global__ void k_finalize(const float* __restrict__ gamma,
                           const float* __restrict__ beta) {
    const int c = threadIdx.x;   // 512 threads
    const float4* p1 = (const float4*)(g_psum + c * B_);
    const float4* p2 = (const float4*)(g_psq  + c * B_);
    float s1 = 0.f, s2 = 0.f;
    #pragma unroll
    for (int k = 0; k < 16; k++) {
        float4 a = p1[k], b = p2[k];
        s1 += (a.x + a.y) + (a.z + a.w);
        s2 += (b.x + b.y) + (b.z + b.w);
    }
    const float invn = 1.0f / 36864.0f;           // 1/(B*NN)
    const float mean = s1 * invn;
    const float var  = s2 * invn - mean * mean;
    const float sc = gamma[c] * rsqrtf(var + BN_EPS);
    g_scale[c] = sc;
    g_shift[c] = beta[c] - mean * sc;
}

extern "C" void kernel_launch(void* const* d_in, const int* in_sizes, int n_in,
                              void* d_out, int out_size) {
    const float* x     = (const float*)d_in[0];   // [64,512,24,24]
    // d_in[1] = adj (unused: grid structure exploited analytically)
    const float* w     = (const float*)d_in[2];   // [512,576]
    const float* gamma = (const float*)d_in[3];   // [512]
    const float* beta  = (const float*)d_in[4];   // [512]
    float* out = (float*)d_out;

    const int nblk = (B_ * C_) / IPB;             // 4096 blocks, 8 images each
    k_main<true ><<<nblk, TPB>>>(x, w, out);
    k_finalize<<<1, C_>>>(gamma, beta);
    k_main<false><<<nblk, TPB>>>(x, w, out);
}

// round 14
// speedup vs baseline: 1.0712x; 1.0712x over previous
#include <cuda_runtime.h>

// Spatial GCN on a 24x24 grid: adj = D^-1 A + I (4-neighbor grid) => 5-point
// stencil with analytic 1/deg(neighbor) in {1/2, 1/3, 1/4}. Then elementwise
// weight, BatchNorm2d (batch stats), LeakyReLU(0.2).
//
// R14: two-pass, CHANNEL-MAJOR blocks (one channel x 8 batches per block):
// weight row loaded ONCE per block; lf/rg neighbors via single warp shuffles
// (bank-conflicted scalar LDS eliminated); up/dn via aligned LDS.128 from an
// 18 KB smem stage. Pass2 recomputes from L2-hot x and streams out.

#define B_   64
#define C_   512
#define NN   576
#define BN_EPS 1e-4f
#define SLOPE  0.2f

#define TPB  288     // 2 slots of 144 threads; slot handles 4 images
#define U_   4
#define IPB  (2*U_)  // 8 images (batches) per block, same channel

__device__ float g_psum[C_ * 8];
__device__ float g_psq [C_ * 8];
__device__ float g_scale[C_];
__device__ float g_shift[C_];

__device__ __forceinline__ float invd(int d) {
    // d in {2,3,4}
    return d == 4 ? 0.25f : (d == 3 ? (1.0f / 3.0f) : 0.5f);
}

template <bool STATS>
__global__ __launch_bounds__(TPB, 5) void k_main(const float* __restrict__ x,
                                                 const float* __restrict__ w,
                                                 float* __restrict__ out) {
    __shared__ float xs[IPB * NN];                 // 18 KB staged images
    __shared__ float red1[9], red2[9];

    const int tid  = threadIdx.x;
    const int lane = tid & 31;
    const int slot = tid >= 144;
    const int r    = tid - 144 * slot;             // chunk 0..143
    const int i    = r / 6;                        // row
    const int q    = r - 6 * i;                    // chunk-in-row
    const int c    = blockIdx.x >> 3;              // channel
    const int bg   = blockIdx.x & 7;               // batch group
    const int b0   = bg * 8 + slot * 4;            // first batch of this slot
    const size_t off0 = ((size_t)b0 * C_ + c) * NN + r * 4;
    const size_t bstride = (size_t)C_ * NN;        // batch stride in floats
    const unsigned FULL = 0xFFFFFFFFu;

    // ---- stencil coefficients (chunk-position only) ----
    const int rti = (i > 0) + (i < 23);
    const int rtu = (i > 1) + 1;                   // rowterm(i-1), valid iff i>0
    const int rtd = 1 + (i < 22);                  // rowterm(i+1), valid iff i<23
    const float cHi = invd(rti + 2);
    const float cHe = invd(rti + 1);
    const float cUi = invd(rtu + 2), cUe = invd(rtu + 1);
    const float cDi = invd(rtd + 2), cDe = invd(rtd + 1);

    const bool q0 = (q == 0), q5 = (q == 5);
    const bool hasU = (i > 0), hasD = (i < 23);
    const float cL0 = q0 ? 0.0f : cHi;
    const float cL1 = q0 ? cHe  : cHi;
    const float cR2 = q5 ? cHe  : cHi;
    const float cR3 = q5 ? 0.0f : cHi;
    const float vU = hasU ? 1.0f : 0.0f;
    const float vD = hasD ? 1.0f : 0.0f;
    const float cU0 = vU * (q0 ? cUe : cUi), cUm = vU * cUi, cU3 = vU * (q5 ? cUe : cUi);
    const float cD0 = vD * (q0 ? cDe : cDi), cDm = vD * cDi, cD3 = vD * (q5 ? cDe : cDi);

    const int upOff = hasU ? -24 : 0;              // clamped (coeff 0 when clamped)
    const int dnOff = hasD ?  24 : 0;
    const bool fbL = (!q0) && (lane == 0);         // lf crosses warp boundary
    const bool fbR = (!q5) && (lane == 31);        // rg crosses warp boundary

    // weight row: ONE load for all 8 images of this block
    const float4 wv = __ldg((const float4*)(w + c * NN + r * 4));

    // ---- batched center loads (MLP=4), stage to smem ----
    float4 ct[U_];
    #pragma unroll
    for (int u = 0; u < U_; u++)
        ct[u] = *(const float4*)(x + off0 + u * bstride);
    #pragma unroll
    for (int u = 0; u < U_; u++)
        *(float4*)(xs + (slot * U_ + u) * NN + r * 4) = ct[u];
    __syncthreads();

    float sc = 0.0f, sh = 0.0f;
    if (!STATS) { sc = __ldg(&g_scale[c]); sh = __ldg(&g_shift[c]); }

    float s1 = 0.0f, s2 = 0.0f;

    #pragma unroll
    for (int u = 0; u < U_; u++) {
        const float* xc = xs + (slot * U_ + u) * NN + r * 4;
        const float4 c4 = ct[u];
        const float4 up = *(const float4*)(xc + upOff);
        const float4 dn = *(const float4*)(xc + dnOff);
        // lf/rg from neighboring lanes (consecutive chunks). At the slot
        // straddle (lane 15->16) source is another image, but that position
        // is q5/q0 where the coefficient is zero.
        float lf = __shfl_up_sync(FULL, c4.w, 1);
        float rg = __shfl_down_sync(FULL, c4.x, 1);
        if (fbL) lf = xc[-1];
        if (fbR) rg = xc[4];

        const float t0 = c4.x + cL0 * lf   + cHi * c4.y + cU0 * up.x + cD0 * dn.x;
        const float t1 = c4.y + cL1 * c4.x + cHi * c4.z + cUm * up.y + cDm * dn.y;
        const float t2 = c4.z + cHi * c4.y + cR2 * c4.w + cUm * up.z + cDm * dn.z;
        const float t3 = c4.w + cHi * c4.z + cR3 * rg   + cU3 * up.w + cD3 * dn.w;

        const float y0 = t0 * wv.x, y1 = t1 * wv.y, y2 = t2 * wv.z, y3 = t3 * wv.w;

        if (STATS) {
            s1 += (y0 + y1) + (y2 + y3);
            s2 += (y0 * y0 + y1 * y1) + (y2 * y2 + y3 * y3);
        } else {
            float n0 = fmaf(y0, sc, sh), n1 = fmaf(y1, sc, sh);
            float n2 = fmaf(y2, sc, sh), n3 = fmaf(y3, sc, sh);
            n0 = (n0 >= 0.f) ? n0 : SLOPE * n0;
            n1 = (n1 >= 0.f) ? n1 : SLOPE * n1;
            n2 = (n2 >= 0.f) ? n2 : SLOPE * n2;
            n3 = (n3 >= 0.f) ? n3 : SLOPE * n3;
            *(float4*)(out + off0 + u * bstride) = make_float4(n0, n1, n2, n3);
        }
    }

    if (STATS) {
        // whole block reduces to ONE (sum, sumsq) for (c, bg) — deterministic
        #pragma unroll
        for (int o = 16; o; o >>= 1) {
            s1 += __shfl_down_sync(FULL, s1, o);
            s2 += __shfl_down_sync(FULL, s2, o);
        }
        const int wid = tid >> 5;
        if (lane == 0) { red1[wid] = s1; red2[wid] = s2; }
        __syncthreads();
        if (tid == 0) {
            float a = 0.f, bb = 0.f;
            #pragma unroll
            for (int k = 0; k < 9; k++) { a += red1[k]; bb += red2[k]; }
            g_psum[c * 8 + bg] = a;
            g_psq [c * 8 + bg] = bb;
        }
    }
}

// ---------------- finalize ----------------
__global__ void k_finalize(const float* __restrict__ gamma,
                           const float* __restrict__ beta) {
    const int c = threadIdx.x;   // 512 threads
    float s1 = 0.f, s2 = 0.f;
    #pragma unroll
    for (int k = 0; k < 8; k++) {
        s1 += g_psum[c * 8 + k];
        s2 += g_psq [c * 8 + k];
    }
    const float invn = 1.0f / 36864.0f;           // 1/(B*NN)
    const float mean = s1 * invn;
    const float var  = s2 * invn - mean * mean;
    const float sc = gamma[c] * rsqrtf(var + BN_EPS);
    g_scale[c] = sc;
    g_shift[c] = beta[c] - mean * sc;
}

extern "C" void kernel_launch(void* const* d_in, const int* in_sizes, int n_in,
                              void* d_out, int out_size) {
    const float* x     = (const float*)d_in[0];   // [64,512,24,24]
    // d_in[1] = adj (unused: grid structure exploited analytically)
    const float* w     = (const float*)d_in[2];   // [512,576]
    const float* gamma = (const float*)d_in[3];   // [512]
    const float* beta  = (const float*)d_in[4];   // [512]
    float* out = (float*)d_out;

    const int nblk = C_ * 8;                      // 4096 blocks
    k_main<true ><<<nblk, TPB>>>(x, w, out);
    k_finalize<<<1, C_>>>(gamma, beta);
    k_main<false><<<nblk, TPB>>>(x, w, out);
}